// round 15
// baseline (speedup 1.0000x reference)
#include <cuda_runtime.h>
#include <cuda_bf16.h>

// ---------------- problem constants ----------------
#define BSZ_B 2
#define T_LEN 100
#define N_OBJ 30
#define BT    (BSZ_B * T_LEN)      // 200
#define MROWS (BT * N_OBJ)         // 6000
#define K1    4096
#define DH1   512
#define DH2   256
#define DFF   512
#define NH    4
#define DHEAD 64

// ---------------- GEMM tiling ----------------
#define TBM 128
#define TBN 128
#define TBK 32
#define NS  4                       // pipeline stages
#define NT  512                     // threads per GEMM CTA (16 warps)
#define LDA_S 36                    // smem A row stride (floats)
#define LDB_S 136                   // smem B row stride (floats)
#define ASZ  (TBM * LDA_S)          // 4608 floats / stage
#define BSZT (TBK * LDB_S)          // 4352 floats / stage
#define GEMM_SMEM (NS * (ASZ + BSZT) * 4)   // 143360 bytes

// ---------------- scratch (device globals; no runtime alloc) ----------------
__device__ __align__(16) float g_Wc1[(K1 + 1) * DH1];   // tf32(W1a - W2a/29)
__device__ __align__(16) float g_W2ar[(K1 + 1) * DH1];  // tf32(W2a)
__device__ __align__(16) float g_Wc2[DH1 * DH2];        // tf32(W1b - W2b/29)
__device__ __align__(16) float g_W2br[DH1 * DH2];       // tf32(W2b)
__device__ __align__(16) float g_S[BT * K1];
__device__ __align__(16) float g_Sdep[BT];
__device__ __align__(16) float g_U1[BT * DH1];
__device__ __align__(16) float g_H1[MROWS * DH1];
__device__ __align__(16) float g_S1[BT * DH1];
__device__ __align__(16) float g_U2[BT * DH2];
__device__ __align__(16) float g_H2[MROWS * DH2];
__device__ __align__(16) float g_gp[BT * DH2];
__device__ __align__(16) float g_q[BT * DH2];
__device__ __align__(16) float g_k[BT * DH2];
__device__ __align__(16) float g_v[BT * DH2];
__device__ __align__(16) float g_att[BT * DH2];
__device__ __align__(16) float g_part[16 * 256 * DH1];  // split-K partials

// ---------------- helpers ----------------
__device__ __forceinline__ unsigned f2tf(float f) {
    unsigned u;
    asm("cvt.rna.tf32.f32 %0, %1;" : "=r"(u) : "f"(f));
    return u;
}

__device__ __forceinline__ void mma_tf32(float* d, const unsigned* a, const unsigned* b) {
    asm volatile(
        "mma.sync.aligned.m16n8k8.row.col.f32.tf32.tf32.f32 "
        "{%0,%1,%2,%3}, {%4,%5,%6,%7}, {%8,%9}, {%0,%1,%2,%3};"
        : "+f"(d[0]), "+f"(d[1]), "+f"(d[2]), "+f"(d[3])
        : "r"(a[0]), "r"(a[1]), "r"(a[2]), "r"(a[3]), "r"(b[0]), "r"(b[1]));
}

__device__ __forceinline__ float blocksum256(float v, float* buf) {
    int tid = threadIdx.x;
    buf[tid] = v;
    __syncthreads();
    for (int s = 128; s > 0; s >>= 1) {
        if (tid < s) buf[tid] += buf[tid + s];
        __syncthreads();
    }
    float r = buf[0];
    __syncthreads();
    return r;
}

// ---------------- prep: combined + tf32-prerounded weights ----------------
__global__ void prep_wc(const float* __restrict__ W1a, const float* __restrict__ W2a,
                        const float* __restrict__ W1b, const float* __restrict__ W2b) {
    const float inv = 1.0f / (N_OBJ - 1);
    int stride = gridDim.x * blockDim.x;
    int n1 = (K1 + 1) * DH1;
    for (int i = blockIdx.x * blockDim.x + threadIdx.x; i < n1; i += stride) {
        float w2 = W2a[i];
        g_Wc1[i]  = __uint_as_float(f2tf(W1a[i] - w2 * inv));
        g_W2ar[i] = __uint_as_float(f2tf(w2));
    }
    int n2 = DH1 * DH2;
    for (int i = blockIdx.x * blockDim.x + threadIdx.x; i < n2; i += stride) {
        float w2 = W2b[i];
        g_Wc2[i]  = __uint_as_float(f2tf(W1b[i] - w2 * inv));
        g_W2br[i] = __uint_as_float(f2tf(w2));
    }
}

// ---------------- column sum over 30 objects (float4 vectorized) ----------------
__global__ void colsum30(const float* __restrict__ src, int ld, float* __restrict__ out,
                         int cols, float scale) {
    int bt = blockIdx.y;
    int c4 = blockIdx.x * blockDim.x + threadIdx.x;
    if (c4 * 4 >= cols) return;
    const float4* p = (const float4*)(src + (size_t)bt * N_OBJ * ld) + c4;
    int ld4 = ld >> 2;
    float4 a = make_float4(0.f, 0.f, 0.f, 0.f);
#pragma unroll
    for (int n = 0; n < N_OBJ; n++) {
        float4 v = p[(size_t)n * ld4];
        a.x += v.x; a.y += v.y; a.z += v.z; a.w += v.w;
    }
    a.x *= scale; a.y *= scale; a.z *= scale; a.w *= scale;
    ((float4*)(out + (size_t)bt * cols))[c4] = a;
}

__global__ void depsum(const float* __restrict__ dep) {
    int bt = blockIdx.x * blockDim.x + threadIdx.x;
    if (bt < BT) {
        float s = 0.f;
#pragma unroll
        for (int n = 0; n < N_OBJ; n++) s += dep[bt * N_OBJ + n];
        g_Sdep[bt] = s * (1.0f / (N_OBJ - 1));
    }
}

// ---------------- tf32 tensor-core GEMM, 512 threads, 4-stage pipeline ---------
// B must be pre-rounded to tf32. A is cvt'd in-loop.
// direct (gridDim.z==1): C = A@B + rvec[m]*extw[n] + grp[m/30][n] + bias[n], relu opt.
// split-K (gridDim.z>1): raw partials to C + z*planeStride.
__global__ void __launch_bounds__(NT)
gemm_tf32(const float* __restrict__ A, int lda,
          const float* __restrict__ B, int ldb,
          float* __restrict__ C, int ldc, int planeStride,
          int M, int N, int K,
          const float* __restrict__ rvec, const float* __restrict__ extw,
          const float* __restrict__ grp, const float* __restrict__ bias,
          int relu) {
    extern __shared__ float smem[];
    float* sA = smem;                 // [NS][TBM][LDA_S]
    float* sB = smem + NS * ASZ;      // [NS][TBK][LDB_S]

    const int tid = threadIdx.x;
    const int bM = blockIdx.y * TBM;
    const int bN = blockIdx.x * TBN;
    const int warp = tid >> 5, lane = tid & 31;
    const int wm = (warp >> 2) * 32;    // 4 warp rows in M
    const int wn = (warp & 3) * 32;     // 4 warp cols in N
    const int qr = lane >> 2, qc = lane & 3;

    float acc[2][4][4];
#pragma unroll
    for (int i = 0; i < 2; i++)
#pragma unroll
        for (int j = 0; j < 4; j++)
#pragma unroll
            for (int e = 0; e < 4; e++) acc[i][j][e] = 0.f;

    const int KTtot = K / TBK;
    int KT = KTtot, kt0 = 0;
    if (gridDim.z > 1) { KT = KTtot / gridDim.z; kt0 = blockIdx.z * KT; }

    auto stage = [&](int buf, int kt) {
#pragma unroll
        for (int i = 0; i < 2; i++) {          // A: 1024 float4
            int id = tid + NT * i;
            int r = id >> 3, c4 = id & 7;
            int gm = bM + r;
            int gmc = gm < M ? gm : (M - 1);
            const float* src = A + (size_t)gmc * lda + (size_t)kt * TBK + c4 * 4;
            unsigned dst = (unsigned)__cvta_generic_to_shared(sA + buf * ASZ + r * LDA_S + c4 * 4);
            int sz = (gm < M) ? 16 : 0;
            asm volatile("cp.async.cg.shared.global [%0], [%1], 16, %2;\n"
                         :: "r"(dst), "l"(src), "r"(sz));
        }
#pragma unroll
        for (int i = 0; i < 2; i++) {          // B: 1024 float4
            int id = tid + NT * i;
            int r = id >> 5, c4 = id & 31;
            const float* src = B + (size_t)(kt * TBK + r) * ldb + bN + c4 * 4;
            unsigned dst = (unsigned)__cvta_generic_to_shared(sB + buf * BSZT + r * LDB_S + c4 * 4);
            asm volatile("cp.async.cg.shared.global [%0], [%1], 16, 16;\n"
                         :: "r"(dst), "l"(src));
        }
        asm volatile("cp.async.commit_group;\n" ::: "memory");
    };

#pragma unroll
    for (int s = 0; s < NS - 1; s++) {
        if (s < KT) stage(s, kt0 + s);
        else asm volatile("cp.async.commit_group;\n" ::: "memory");
    }

    for (int kt = 0; kt < KT; kt++) {
        asm volatile("cp.async.wait_group %0;\n" :: "n"(NS - 2) : "memory");
        __syncthreads();

        int nk = kt + NS - 1;
        if (nk < KT) stage(nk % NS, kt0 + nk);
        else asm volatile("cp.async.commit_group;\n" ::: "memory");

        const float* As = sA + (kt % NS) * ASZ;
        const unsigned* Bs = (const unsigned*)(sB + (kt % NS) * BSZT);

#pragma unroll
        for (int ks = 0; ks < 4; ks++) {
            const int k0 = ks * 8;
            unsigned af[2][4], bf[4][2];
#pragma unroll
            for (int i = 0; i < 2; i++) {
                int r = wm + i * 16 + qr;
                af[i][0] = f2tf(As[r * LDA_S + k0 + qc]);
                af[i][1] = f2tf(As[(r + 8) * LDA_S + k0 + qc]);
                af[i][2] = f2tf(As[r * LDA_S + k0 + qc + 4]);
                af[i][3] = f2tf(As[(r + 8) * LDA_S + k0 + qc + 4]);
            }
#pragma unroll
            for (int j = 0; j < 4; j++) {
                int c = wn + j * 8 + qr;
                bf[j][0] = Bs[(k0 + qc) * LDB_S + c];          // pre-rounded tf32
                bf[j][1] = Bs[(k0 + qc + 4) * LDB_S + c];
            }
#pragma unroll
            for (int i = 0; i < 2; i++)
#pragma unroll
                for (int j = 0; j < 4; j++) mma_tf32(acc[i][j], af[i], bf[j]);
        }
    }

    float* Cout = C + (gridDim.z > 1 ? (size_t)blockIdx.z * planeStride : 0);
    const int raw = (gridDim.z > 1);
#pragma unroll
    for (int i = 0; i < 2; i++) {
        int m0 = bM + wm + i * 16 + qr;
#pragma unroll
        for (int j = 0; j < 4; j++) {
            int n0 = bN + wn + j * 8 + qc * 2;
#pragma unroll
            for (int r2 = 0; r2 < 2; r2++) {
                int m = m0 + r2 * 8;
                if (m < M) {
#pragma unroll
                    for (int c2 = 0; c2 < 2; c2++) {
                        int n = n0 + c2;
                        float v = acc[i][j][r2 * 2 + c2];
                        if (!raw) {
                            if (rvec) v += rvec[m] * extw[n];
                            if (grp)  v += grp[(size_t)(m / N_OBJ) * ldc + n];
                            if (bias) v += bias[n];
                            if (relu) v = fmaxf(v, 0.f);
                        }
                        Cout[(size_t)m * ldc + n] = v;
                    }
                }
            }
        }
    }
}

// ---------------- split-K reduce with epilogue ----------------
__global__ void splitk_reduce(const float* __restrict__ part, int planes, int planeStride,
                              float* __restrict__ C, int M, int N,
                              const float* __restrict__ rvec, const float* __restrict__ extw,
                              const float* __restrict__ bias) {
    int idx = blockIdx.x * blockDim.x + threadIdx.x;
    if (idx >= M * N) return;
    int m = idx / N, n = idx - m * N;
    float s = 0.f;
    for (int z = 0; z < planes; z++) s += part[(size_t)z * planeStride + (size_t)m * N + n];
    if (rvec) s += rvec[m] * extw[n];
    if (bias) s += bias[n];
    C[(size_t)m * N + n] = s;
}

// ---------------- fused q/k/v projection ----------------
__global__ void qkv_kernel(const float* __restrict__ g, const float* __restrict__ Wq,
                           const float* __restrict__ Wk, const float* __restrict__ Wv,
                           float* __restrict__ q, float* __restrict__ k,
                           float* __restrict__ v) {
    __shared__ float sg[DH2];
    int m = blockIdx.x, tid = threadIdx.x;
    sg[tid] = g[(size_t)m * DH2 + tid];
    __syncthreads();
    float aq = 0.f, ak = 0.f, av = 0.f;
#pragma unroll 4
    for (int kk = 0; kk < DH2; kk++) {
        float x = sg[kk];
        aq += x * Wq[(size_t)kk * DH2 + tid];
        ak += x * Wk[(size_t)kk * DH2 + tid];
        av += x * Wv[(size_t)kk * DH2 + tid];
    }
    q[(size_t)m * DH2 + tid] = aq;
    k[(size_t)m * DH2 + tid] = ak;
    v[(size_t)m * DH2 + tid] = av;
}

// ---------------- attention ----------------
__global__ void attn_kernel(const float* __restrict__ q, const float* __restrict__ k,
                            const float* __restrict__ v, float* __restrict__ o) {
    int t = blockIdx.x;
    int bh = blockIdx.y;
    int b = bh >> 2, h = bh & 3;
    __shared__ float sq[DHEAD];
    __shared__ float sp[128];
    __shared__ float buf[128];
    int tid = threadIdx.x;
    int rowbase = (b * T_LEN + t) * DH2 + h * DHEAD;
    if (tid < DHEAD) sq[tid] = q[rowbase + tid];
    __syncthreads();
    float sc = -1e30f;
    if (tid < T_LEN) {
        const float* kr = k + (b * T_LEN + tid) * DH2 + h * DHEAD;
        float d = 0.f;
#pragma unroll
        for (int j = 0; j < DHEAD; j++) d += sq[j] * kr[j];
        sc = d * 0.125f;
    }
    buf[tid] = sc;
    __syncthreads();
    for (int s = 64; s > 0; s >>= 1) {
        if (tid < s) buf[tid] = fmaxf(buf[tid], buf[tid + s]);
        __syncthreads();
    }
    float mx = buf[0];
    __syncthreads();
    float e = (tid < T_LEN) ? expf(sc - mx) : 0.f;
    buf[tid] = e;
    __syncthreads();
    for (int s = 64; s > 0; s >>= 1) {
        if (tid < s) buf[tid] += buf[tid + s];
        __syncthreads();
    }
    float inv = 1.f / buf[0];
    __syncthreads();
    sp[tid] = e * inv;
    __syncthreads();
    if (tid < DHEAD) {
        float a = 0.f;
        for (int s = 0; s < T_LEN; s++)
            a += sp[s] * v[(b * T_LEN + s) * DH2 + h * DHEAD + tid];
        o[rowbase + tid] = a;
    }
}

// ---------------- fused tail ----------------
__global__ void tail_kernel(const float* __restrict__ att, const float* __restrict__ g,
                            const float* __restrict__ Wo,
                            const float* __restrict__ ln1g, const float* __restrict__ ln1b,
                            const float* __restrict__ Wf1, const float* __restrict__ bf1,
                            const float* __restrict__ Wf2, const float* __restrict__ bf2,
                            const float* __restrict__ ln2g, const float* __restrict__ ln2b,
                            const float* __restrict__ Wc, const float* __restrict__ bc,
                            float* __restrict__ out) {
    __shared__ float sctx[DH2];
    __shared__ float sy[DH2];
    __shared__ float sff[DFF];
    __shared__ float buf[256];
    int m = blockIdx.x, tid = threadIdx.x;

    sctx[tid] = att[(size_t)m * DH2 + tid];
    __syncthreads();
    float p = 0.f;
#pragma unroll 4
    for (int kk = 0; kk < DH2; kk++) p += sctx[kk] * Wo[(size_t)kk * DH2 + tid];
    float v = g[(size_t)m * DH2 + tid] + p;
    float mu = blocksum256(v, buf) * (1.f / DH2);
    float d = v - mu;
    float var = blocksum256(d * d, buf) * (1.f / DH2);
    float y = d * rsqrtf(var + 1e-5f) * ln1g[tid] + ln1b[tid];
    sy[tid] = y;
    __syncthreads();
#pragma unroll
    for (int jj = 0; jj < 2; jj++) {
        int j = tid + jj * 256;
        float a = 0.f;
#pragma unroll 4
        for (int kk = 0; kk < DH2; kk++) a += sy[kk] * Wf1[(size_t)kk * DFF + j];
        sff[j] = fmaxf(a + bf1[j], 0.f);
    }
    __syncthreads();
    float a2 = 0.f;
#pragma unroll 4
    for (int kk = 0; kk < DFF; kk++) a2 += sff[kk] * Wf2[(size_t)kk * DH2 + tid];
    a2 += bf2[tid];
    float v2 = y + a2;
    float mu2 = blocksum256(v2, buf) * (1.f / DH2);
    float d2 = v2 - mu2;
    float var2 = blocksum256(d2 * d2, buf) * (1.f / DH2);
    float z = d2 * rsqrtf(var2 + 1e-5f) * ln2g[tid] + ln2b[tid];
    float s = blocksum256(z * Wc[tid], buf);
    if (tid == 0) out[m] = 1.f / (1.f + expf(-(s + bc[0])));
}

__global__ void zerofill(float* __restrict__ p, int n) {
    int i = blockIdx.x * blockDim.x + threadIdx.x;
    if (i < n) p[i] = 0.f;
}

static inline int cs_grid(int cols) {
    int v = (cols / 4 + 127) / 128;
    return v < 1 ? 1 : v;
}

// ---------------- launch ----------------
extern "C" void kernel_launch(void* const* d_in, const int* in_sizes, int n_in,
                              void* d_out, int out_size) {
    const float* feat = (const float*)d_in[0];
    const float* dep  = (const float*)d_in[1];
    const float* W1a = (const float*)d_in[2];
    const float* W2a = (const float*)d_in[3];
    const float* b1a = (const float*)d_in[4];
    const float* W1b = (const float*)d_in[5];
    const float* W2b = (const float*)d_in[6];
    const float* b1b = (const float*)d_in[7];
    const float* Wq = (const float*)d_in[8];
    const float* Wk = (const float*)d_in[9];
    const float* Wv = (const float*)d_in[10];
    const float* Wo = (const float*)d_in[11];
    const float* ln1g = (const float*)d_in[12];
    const float* ln1b = (const float*)d_in[13];
    const float* Wf1 = (const float*)d_in[14];
    const float* bf1 = (const float*)d_in[15];
    const float* Wf2 = (const float*)d_in[16];
    const float* bf2 = (const float*)d_in[17];
    const float* ln2g = (const float*)d_in[18];
    const float* ln2b = (const float*)d_in[19];
    const float* Wc = (const float*)d_in[20];
    const float* bc = (const float*)d_in[21];
    float* out = (float*)d_out;

    float *pWc1, *pW2ar, *pWc2, *pW2br, *pS, *pSdep, *pU1, *pH1, *pS1, *pU2, *pH2, *pg;
    float *pq, *pk, *pv, *patt, *ppart;
    cudaGetSymbolAddress((void**)&pWc1, g_Wc1);
    cudaGetSymbolAddress((void**)&pW2ar, g_W2ar);
    cudaGetSymbolAddress((void**)&pWc2, g_Wc2);
    cudaGetSymbolAddress((void**)&pW2br, g_W2br);
    cudaGetSymbolAddress((void**)&pS, g_S);
    cudaGetSymbolAddress((void**)&pSdep, g_Sdep);
    cudaGetSymbolAddress((void**)&pU1, g_U1);
    cudaGetSymbolAddress((void**)&pH1, g_H1);
    cudaGetSymbolAddress((void**)&pS1, g_S1);
    cudaGetSymbolAddress((void**)&pU2, g_U2);
    cudaGetSymbolAddress((void**)&pH2, g_H2);
    cudaGetSymbolAddress((void**)&pg, g_gp);
    cudaGetSymbolAddress((void**)&pq, g_q);
    cudaGetSymbolAddress((void**)&pk, g_k);
    cudaGetSymbolAddress((void**)&pv, g_v);
    cudaGetSymbolAddress((void**)&patt, g_att);
    cudaGetSymbolAddress((void**)&ppart, g_part);

    cudaFuncSetAttribute((const void*)gemm_tf32,
                         cudaFuncAttributeMaxDynamicSharedMemorySize, GEMM_SMEM);

    // combined + pre-rounded weights, neighbor sums
    prep_wc<<<1024, 256>>>(W1a, W2a, W1b, W2b);
    colsum30<<<dim3(cs_grid(K1), BT), 128>>>(feat, K1, pS, K1, 1.0f / (N_OBJ - 1));
    depsum<<<1, 256>>>(dep);

    // U1 = (S/29) @ W2a  (split-K=16, reduce adds Sdep rank-1 + b1a)
    {
        int planeStride = 2 * TBM * DH1;
        gemm_tf32<<<dim3(DH1 / TBN, 2, 16), NT, GEMM_SMEM>>>(
            pS, K1, pW2ar, DH1, ppart, DH1, planeStride, BT, DH1, K1,
            nullptr, nullptr, nullptr, nullptr, 0);
        splitk_reduce<<<(BT * DH1 + 255) / 256, 256>>>(
            ppart, 16, planeStride, pU1, BT, DH1,
            pSdep, W2a + (size_t)K1 * DH1, b1a);
    }

    // H1 = relu(X @ Wc1 + depth*Wc1row4096 + U1[bt])
    gemm_tf32<<<dim3(DH1 / TBN, (MROWS + TBM - 1) / TBM, 1), NT, GEMM_SMEM>>>(
        feat, K1, pWc1, DH1, pH1, DH1, 0, MROWS, DH1, K1,
        dep, pWc1 + (size_t)K1 * DH1, pU1, nullptr, 1);

    // layer b
    colsum30<<<dim3(cs_grid(DH1), BT), 128>>>(pH1, DH1, pS1, DH1, 1.0f / (N_OBJ - 1));
    {
        int planeStride = 2 * TBM * DH2;
        gemm_tf32<<<dim3(DH2 / TBN, 2, 8), NT, GEMM_SMEM>>>(
            pS1, DH1, pW2br, DH2, ppart, DH2, planeStride, BT, DH2, DH1,
            nullptr, nullptr, nullptr, nullptr, 0);
        splitk_reduce<<<(BT * DH2 + 255) / 256, 256>>>(
            ppart, 8, planeStride, pU2, BT, DH2, nullptr, nullptr, b1b);
    }
    gemm_tf32<<<dim3(DH2 / TBN, (MROWS + TBM - 1) / TBM, 1), NT, GEMM_SMEM>>>(
        pH1, DH1, pWc2, DH2, pH2, DH2, 0, MROWS, DH2, DH1,
        nullptr, nullptr, pU2, nullptr, 1);

    // pool
    colsum30<<<dim3(cs_grid(DH2), BT), 128>>>(pH2, DH2, pg, DH2, 1.0f / N_OBJ);

    // transformer (fused)
    qkv_kernel<<<BT, 256>>>(pg, Wq, Wk, Wv, pq, pk, pv);
    attn_kernel<<<dim3(T_LEN, BSZ_B * NH), 128>>>(pq, pk, pv, patt);
    tail_kernel<<<BT, 256>>>(patt, pg, Wo, ln1g, ln1b, Wf1, bf1, Wf2, bf2,
                             ln2g, ln2b, Wc, bc, out);

    if (out_size > BT) {
        int rem = out_size - BT;
        zerofill<<<(rem + 255) / 256, 256>>>(out + BT, rem);
    }
}

// round 16
// speedup vs baseline: 1.1729x; 1.1729x over previous
#include <cuda_runtime.h>
#include <cuda_bf16.h>

// ---------------- problem constants ----------------
#define BSZ_B 2
#define T_LEN 100
#define N_OBJ 30
#define BT    (BSZ_B * T_LEN)      // 200
#define MROWS (BT * N_OBJ)         // 6000
#define K1    4096
#define DH1   512
#define DH2   256
#define DFF   512
#define NH    4
#define DHEAD 64

// ---------------- GEMM tiling ----------------
#define TBM 128
#define TBN 128
#define TBK 32
#define NS  3                       // pipeline stages
#define LDA_S 36                    // smem A row stride (floats)
#define LDB_S 136                   // smem B row stride (floats)
#define ASZ  (TBM * LDA_S)          // 4608 floats / stage
#define BSZT (TBK * LDB_S)          // 4352 floats / stage
#define GEMM_SMEM (NS * (ASZ + BSZT) * 4)   // 107520 bytes -> 2 CTAs/SM

// ---------------- scratch (device globals; no runtime alloc) ----------------
__device__ __align__(16) float g_Wc1[(K1 + 1) * DH1];   // tf32(W1a - W2a/29)
__device__ __align__(16) float g_W2ar[(K1 + 1) * DH1];  // tf32(W2a)
__device__ __align__(16) float g_Wc2[DH1 * DH2];        // tf32(W1b - W2b/29)
__device__ __align__(16) float g_W2br[DH1 * DH2];       // tf32(W2b)
__device__ __align__(16) float g_S[BT * K1];
__device__ __align__(16) float g_Sdep[BT];
__device__ __align__(16) float g_U1[BT * DH1];
__device__ __align__(16) float g_H1[MROWS * DH1];
__device__ __align__(16) float g_S1[BT * DH1];
__device__ __align__(16) float g_U2[BT * DH2];
__device__ __align__(16) float g_H2[MROWS * DH2];
__device__ __align__(16) float g_gp[BT * DH2];
__device__ __align__(16) float g_q[BT * DH2];
__device__ __align__(16) float g_k[BT * DH2];
__device__ __align__(16) float g_v[BT * DH2];
__device__ __align__(16) float g_att[BT * DH2];
__device__ __align__(16) float g_part[2 * MROWS * DH1]; // split-K partials (24.6MB)

// ---------------- helpers ----------------
__device__ __forceinline__ unsigned f2tf(float f) {
    unsigned u;
    asm("cvt.rna.tf32.f32 %0, %1;" : "=r"(u) : "f"(f));
    return u;
}

__device__ __forceinline__ void mma_tf32(float* d, const unsigned* a, const unsigned* b) {
    asm volatile(
        "mma.sync.aligned.m16n8k8.row.col.f32.tf32.tf32.f32 "
        "{%0,%1,%2,%3}, {%4,%5,%6,%7}, {%8,%9}, {%0,%1,%2,%3};"
        : "+f"(d[0]), "+f"(d[1]), "+f"(d[2]), "+f"(d[3])
        : "r"(a[0]), "r"(a[1]), "r"(a[2]), "r"(a[3]), "r"(b[0]), "r"(b[1]));
}

__device__ __forceinline__ float blocksum256(float v, float* buf) {
    int tid = threadIdx.x;
    buf[tid] = v;
    __syncthreads();
    for (int s = 128; s > 0; s >>= 1) {
        if (tid < s) buf[tid] += buf[tid + s];
        __syncthreads();
    }
    float r = buf[0];
    __syncthreads();
    return r;
}

// ---------------- prep: combined + tf32-prerounded weights ----------------
__global__ void prep_wc(const float* __restrict__ W1a, const float* __restrict__ W2a,
                        const float* __restrict__ W1b, const float* __restrict__ W2b) {
    const float inv = 1.0f / (N_OBJ - 1);
    int stride = gridDim.x * blockDim.x;
    int n1 = (K1 + 1) * DH1;
    for (int i = blockIdx.x * blockDim.x + threadIdx.x; i < n1; i += stride) {
        float w2 = W2a[i];
        g_Wc1[i]  = __uint_as_float(f2tf(W1a[i] - w2 * inv));
        g_W2ar[i] = __uint_as_float(f2tf(w2));
    }
    int n2 = DH1 * DH2;
    for (int i = blockIdx.x * blockDim.x + threadIdx.x; i < n2; i += stride) {
        float w2 = W2b[i];
        g_Wc2[i]  = __uint_as_float(f2tf(W1b[i] - w2 * inv));
        g_W2br[i] = __uint_as_float(f2tf(w2));
    }
}

// ---------------- column sum over 30 objects (float4 vectorized) ----------------
__global__ void colsum30(const float* __restrict__ src, int ld, float* __restrict__ out,
                         int cols, float scale) {
    int bt = blockIdx.y;
    int c4 = blockIdx.x * blockDim.x + threadIdx.x;
    if (c4 * 4 >= cols) return;
    const float4* p = (const float4*)(src + (size_t)bt * N_OBJ * ld) + c4;
    int ld4 = ld >> 2;
    float4 a = make_float4(0.f, 0.f, 0.f, 0.f);
#pragma unroll
    for (int n = 0; n < N_OBJ; n++) {
        float4 v = p[(size_t)n * ld4];
        a.x += v.x; a.y += v.y; a.z += v.z; a.w += v.w;
    }
    a.x *= scale; a.y *= scale; a.z *= scale; a.w *= scale;
    ((float4*)(out + (size_t)bt * cols))[c4] = a;
}

__global__ void depsum(const float* __restrict__ dep) {
    int bt = blockIdx.x * blockDim.x + threadIdx.x;
    if (bt < BT) {
        float s = 0.f;
#pragma unroll
        for (int n = 0; n < N_OBJ; n++) s += dep[bt * N_OBJ + n];
        g_Sdep[bt] = s * (1.0f / (N_OBJ - 1));
    }
}

// ---------------- tf32 tensor-core GEMM, 3-stage pipeline, 2 CTAs/SM -----------
// B must be pre-rounded to tf32. A is cvt'd in-loop.
// direct (gridDim.z==1): C = A@B + rvec[m]*extw[n] + grp[m/30][n] + bias[n], relu opt.
// split-K (gridDim.z>1): raw partials to C + z*planeStride (no epilogue).
__global__ void __launch_bounds__(256, 2)
gemm_tf32(const float* __restrict__ A, int lda,
          const float* __restrict__ B, int ldb,
          float* __restrict__ C, int ldc, int planeStride,
          int M, int N, int K,
          const float* __restrict__ rvec, const float* __restrict__ extw,
          const float* __restrict__ grp, const float* __restrict__ bias,
          int relu) {
    extern __shared__ float smem[];
    float* sA = smem;                 // [NS][TBM][LDA_S]
    float* sB = smem + NS * ASZ;      // [NS][TBK][LDB_S]

    const int tid = threadIdx.x;
    const int bM = blockIdx.y * TBM;
    const int bN = blockIdx.x * TBN;
    const int warp = tid >> 5, lane = tid & 31;
    const int wm = (warp >> 1) * 32;    // 4 warps in M
    const int wn = (warp & 1) * 64;     // 2 warps in N
    const int qr = lane >> 2, qc = lane & 3;

    float acc[2][8][4];
#pragma unroll
    for (int i = 0; i < 2; i++)
#pragma unroll
        for (int j = 0; j < 8; j++)
#pragma unroll
            for (int e = 0; e < 4; e++) acc[i][j][e] = 0.f;

    const int KTtot = K / TBK;
    int KT = KTtot, kt0 = 0;
    if (gridDim.z > 1) { KT = KTtot / gridDim.z; kt0 = blockIdx.z * KT; }

    auto stage = [&](int buf, int kt) {
#pragma unroll
        for (int i = 0; i < 4; i++) {          // A: 1024 float4
            int id = tid + 256 * i;
            int r = id >> 3, c4 = id & 7;
            int gm = bM + r;
            int gmc = gm < M ? gm : (M - 1);
            const float* src = A + (size_t)gmc * lda + (size_t)kt * TBK + c4 * 4;
            unsigned dst = (unsigned)__cvta_generic_to_shared(sA + buf * ASZ + r * LDA_S + c4 * 4);
            int sz = (gm < M) ? 16 : 0;
            asm volatile("cp.async.cg.shared.global [%0], [%1], 16, %2;\n"
                         :: "r"(dst), "l"(src), "r"(sz));
        }
#pragma unroll
        for (int i = 0; i < 4; i++) {          // B: 1024 float4
            int id = tid + 256 * i;
            int r = id >> 5, c4 = id & 31;
            const float* src = B + (size_t)(kt * TBK + r) * ldb + bN + c4 * 4;
            unsigned dst = (unsigned)__cvta_generic_to_shared(sB + buf * BSZT + r * LDB_S + c4 * 4);
            asm volatile("cp.async.cg.shared.global [%0], [%1], 16, 16;\n"
                         :: "r"(dst), "l"(src));
        }
        asm volatile("cp.async.commit_group;\n" ::: "memory");
    };

#pragma unroll
    for (int s = 0; s < NS - 1; s++) {
        if (s < KT) stage(s, kt0 + s);
        else asm volatile("cp.async.commit_group;\n" ::: "memory");
    }

    for (int kt = 0; kt < KT; kt++) {
        asm volatile("cp.async.wait_group %0;\n" :: "n"(NS - 2) : "memory");
        __syncthreads();

        int nk = kt + NS - 1;
        if (nk < KT) stage(nk % NS, kt0 + nk);
        else asm volatile("cp.async.commit_group;\n" ::: "memory");

        const float* As = sA + (kt % NS) * ASZ;
        const unsigned* Bs = (const unsigned*)(sB + (kt % NS) * BSZT);

#pragma unroll
        for (int ks = 0; ks < 4; ks++) {
            const int k0 = ks * 8;
            unsigned af[2][4], bf[8][2];
#pragma unroll
            for (int i = 0; i < 2; i++) {
                int r = wm + i * 16 + qr;
                af[i][0] = f2tf(As[r * LDA_S + k0 + qc]);
                af[i][1] = f2tf(As[(r + 8) * LDA_S + k0 + qc]);
                af[i][2] = f2tf(As[r * LDA_S + k0 + qc + 4]);
                af[i][3] = f2tf(As[(r + 8) * LDA_S + k0 + qc + 4]);
            }
#pragma unroll
            for (int j = 0; j < 8; j++) {
                int c = wn + j * 8 + qr;
                bf[j][0] = Bs[(k0 + qc) * LDB_S + c];          // pre-rounded tf32
                bf[j][1] = Bs[(k0 + qc + 4) * LDB_S + c];
            }
#pragma unroll
            for (int i = 0; i < 2; i++)
#pragma unroll
                for (int j = 0; j < 8; j++) mma_tf32(acc[i][j], af[i], bf[j]);
        }
    }

    float* Cout = C + (gridDim.z > 1 ? (size_t)blockIdx.z * planeStride : 0);
    const int raw = (gridDim.z > 1);
#pragma unroll
    for (int i = 0; i < 2; i++) {
        int m0 = bM + wm + i * 16 + qr;
#pragma unroll
        for (int j = 0; j < 8; j++) {
            int n0 = bN + wn + j * 8 + qc * 2;
#pragma unroll
            for (int r2 = 0; r2 < 2; r2++) {
                int m = m0 + r2 * 8;
                if (m < M) {
#pragma unroll
                    for (int c2 = 0; c2 < 2; c2++) {
                        int n = n0 + c2;
                        float v = acc[i][j][r2 * 2 + c2];
                        if (!raw) {
                            if (rvec) v += rvec[m] * extw[n];
                            if (grp)  v += grp[(size_t)(m / N_OBJ) * ldc + n];
                            if (bias) v += bias[n];
                            if (relu) v = fmaxf(v, 0.f);
                        }
                        Cout[(size_t)m * ldc + n] = v;
                    }
                }
            }
        }
    }
}

// ---------------- split-K reduce with full epilogue ----------------
// C[m][n] = sum_z part[z] (+ rvec[m]*extw[n]) (+ grp[m/30][n]) (+ bias[n]) (relu)
__global__ void splitk_reduce(const float* __restrict__ part, int planes, int planeStride,
                              float* __restrict__ C, int M, int N,
                              const float* __restrict__ rvec, const float* __restrict__ extw,
                              const float* __restrict__ grp, const float* __restrict__ bias,
                              int relu) {
    int idx = blockIdx.x * blockDim.x + threadIdx.x;
    if (idx >= M * N) return;
    int m = idx / N, n = idx - m * N;
    float s = 0.f;
    for (int z = 0; z < planes; z++) s += part[(size_t)z * planeStride + (size_t)m * N + n];
    if (rvec) s += rvec[m] * extw[n];
    if (grp)  s += grp[(size_t)(m / N_OBJ) * N + n];
    if (bias) s += bias[n];
    if (relu) s = fmaxf(s, 0.f);
    C[(size_t)m * N + n] = s;
}

// ---------------- fused q/k/v projection ----------------
__global__ void qkv_kernel(const float* __restrict__ g, const float* __restrict__ Wq,
                           const float* __restrict__ Wk, const float* __restrict__ Wv,
                           float* __restrict__ q, float* __restrict__ k,
                           float* __restrict__ v) {
    __shared__ float sg[DH2];
    int m = blockIdx.x, tid = threadIdx.x;
    sg[tid] = g[(size_t)m * DH2 + tid];
    __syncthreads();
    float aq = 0.f, ak = 0.f, av = 0.f;
#pragma unroll 4
    for (int kk = 0; kk < DH2; kk++) {
        float x = sg[kk];
        aq += x * Wq[(size_t)kk * DH2 + tid];
        ak += x * Wk[(size_t)kk * DH2 + tid];
        av += x * Wv[(size_t)kk * DH2 + tid];
    }
    q[(size_t)m * DH2 + tid] = aq;
    k[(size_t)m * DH2 + tid] = ak;
    v[(size_t)m * DH2 + tid] = av;
}

// ---------------- attention ----------------
__global__ void attn_kernel(const float* __restrict__ q, const float* __restrict__ k,
                            const float* __restrict__ v, float* __restrict__ o) {
    int t = blockIdx.x;
    int bh = blockIdx.y;
    int b = bh >> 2, h = bh & 3;
    __shared__ float sq[DHEAD];
    __shared__ float sp[128];
    __shared__ float buf[128];
    int tid = threadIdx.x;
    int rowbase = (b * T_LEN + t) * DH2 + h * DHEAD;
    if (tid < DHEAD) sq[tid] = q[rowbase + tid];
    __syncthreads();
    float sc = -1e30f;
    if (tid < T_LEN) {
        const float* kr = k + (b * T_LEN + tid) * DH2 + h * DHEAD;
        float d = 0.f;
#pragma unroll
        for (int j = 0; j < DHEAD; j++) d += sq[j] * kr[j];
        sc = d * 0.125f;
    }
    buf[tid] = sc;
    __syncthreads();
    for (int s = 64; s > 0; s >>= 1) {
        if (tid < s) buf[tid] = fmaxf(buf[tid], buf[tid + s]);
        __syncthreads();
    }
    float mx = buf[0];
    __syncthreads();
    float e = (tid < T_LEN) ? expf(sc - mx) : 0.f;
    buf[tid] = e;
    __syncthreads();
    for (int s = 64; s > 0; s >>= 1) {
        if (tid < s) buf[tid] += buf[tid + s];
        __syncthreads();
    }
    float inv = 1.f / buf[0];
    __syncthreads();
    sp[tid] = e * inv;
    __syncthreads();
    if (tid < DHEAD) {
        float a = 0.f;
        for (int s = 0; s < T_LEN; s++)
            a += sp[s] * v[(b * T_LEN + s) * DH2 + h * DHEAD + tid];
        o[rowbase + tid] = a;
    }
}

// ---------------- fused tail ----------------
__global__ void tail_kernel(const float* __restrict__ att, const float* __restrict__ g,
                            const float* __restrict__ Wo,
                            const float* __restrict__ ln1g, const float* __restrict__ ln1b,
                            const float* __restrict__ Wf1, const float* __restrict__ bf1,
                            const float* __restrict__ Wf2, const float* __restrict__ bf2,
                            const float* __restrict__ ln2g, const float* __restrict__ ln2b,
                            const float* __restrict__ Wc, const float* __restrict__ bc,
                            float* __restrict__ out) {
    __shared__ float sctx[DH2];
    __shared__ float sy[DH2];
    __shared__ float sff[DFF];
    __shared__ float buf[256];
    int m = blockIdx.x, tid = threadIdx.x;

    sctx[tid] = att[(size_t)m * DH2 + tid];
    __syncthreads();
    float p = 0.f;
#pragma unroll 4
    for (int kk = 0; kk < DH2; kk++) p += sctx[kk] * Wo[(size_t)kk * DH2 + tid];
    float v = g[(size_t)m * DH2 + tid] + p;
    float mu = blocksum256(v, buf) * (1.f / DH2);
    float d = v - mu;
    float var = blocksum256(d * d, buf) * (1.f / DH2);
    float y = d * rsqrtf(var + 1e-5f) * ln1g[tid] + ln1b[tid];
    sy[tid] = y;
    __syncthreads();
#pragma unroll
    for (int jj = 0; jj < 2; jj++) {
        int j = tid + jj * 256;
        float a = 0.f;
#pragma unroll 4
        for (int kk = 0; kk < DH2; kk++) a += sy[kk] * Wf1[(size_t)kk * DFF + j];
        sff[j] = fmaxf(a + bf1[j], 0.f);
    }
    __syncthreads();
    float a2 = 0.f;
#pragma unroll 4
    for (int kk = 0; kk < DFF; kk++) a2 += sff[kk] * Wf2[(size_t)kk * DH2 + tid];
    a2 += bf2[tid];
    float v2 = y + a2;
    float mu2 = blocksum256(v2, buf) * (1.f / DH2);
    float d2 = v2 - mu2;
    float var2 = blocksum256(d2 * d2, buf) * (1.f / DH2);
    float z = d2 * rsqrtf(var2 + 1e-5f) * ln2g[tid] + ln2b[tid];
    float s = blocksum256(z * Wc[tid], buf);
    if (tid == 0) out[m] = 1.f / (1.f + expf(-(s + bc[0])));
}

__global__ void zerofill(float* __restrict__ p, int n) {
    int i = blockIdx.x * blockDim.x + threadIdx.x;
    if (i < n) p[i] = 0.f;
}

static inline int cs_grid(int cols) {
    int v = (cols / 4 + 127) / 128;
    return v < 1 ? 1 : v;
}

// ---------------- launch ----------------
extern "C" void kernel_launch(void* const* d_in, const int* in_sizes, int n_in,
                              void* d_out, int out_size) {
    const float* feat = (const float*)d_in[0];
    const float* dep  = (const float*)d_in[1];
    const float* W1a = (const float*)d_in[2];
    const float* W2a = (const float*)d_in[3];
    const float* b1a = (const float*)d_in[4];
    const float* W1b = (const float*)d_in[5];
    const float* W2b = (const float*)d_in[6];
    const float* b1b = (const float*)d_in[7];
    const float* Wq = (const float*)d_in[8];
    const float* Wk = (const float*)d_in[9];
    const float* Wv = (const float*)d_in[10];
    const float* Wo = (const float*)d_in[11];
    const float* ln1g = (const float*)d_in[12];
    const float* ln1b = (const float*)d_in[13];
    const float* Wf1 = (const float*)d_in[14];
    const float* bf1 = (const float*)d_in[15];
    const float* Wf2 = (const float*)d_in[16];
    const float* bf2 = (const float*)d_in[17];
    const float* ln2g = (const float*)d_in[18];
    const float* ln2b = (const float*)d_in[19];
    const float* Wc = (const float*)d_in[20];
    const float* bc = (const float*)d_in[21];
    float* out = (float*)d_out;

    float *pWc1, *pW2ar, *pWc2, *pW2br, *pS, *pSdep, *pU1, *pH1, *pS1, *pU2, *pH2, *pg;
    float *pq, *pk, *pv, *patt, *ppart;
    cudaGetSymbolAddress((void**)&pWc1, g_Wc1);
    cudaGetSymbolAddress((void**)&pW2ar, g_W2ar);
    cudaGetSymbolAddress((void**)&pWc2, g_Wc2);
    cudaGetSymbolAddress((void**)&pW2br, g_W2br);
    cudaGetSymbolAddress((void**)&pS, g_S);
    cudaGetSymbolAddress((void**)&pSdep, g_Sdep);
    cudaGetSymbolAddress((void**)&pU1, g_U1);
    cudaGetSymbolAddress((void**)&pH1, g_H1);
    cudaGetSymbolAddress((void**)&pS1, g_S1);
    cudaGetSymbolAddress((void**)&pU2, g_U2);
    cudaGetSymbolAddress((void**)&pH2, g_H2);
    cudaGetSymbolAddress((void**)&pg, g_gp);
    cudaGetSymbolAddress((void**)&pq, g_q);
    cudaGetSymbolAddress((void**)&pk, g_k);
    cudaGetSymbolAddress((void**)&pv, g_v);
    cudaGetSymbolAddress((void**)&patt, g_att);
    cudaGetSymbolAddress((void**)&ppart, g_part);

    cudaFuncSetAttribute((const void*)gemm_tf32,
                         cudaFuncAttributeMaxDynamicSharedMemorySize, GEMM_SMEM);

    // combined + pre-rounded weights, neighbor sums
    prep_wc<<<1024, 256>>>(W1a, W2a, W1b, W2b);
    colsum30<<<dim3(cs_grid(K1), BT), 128>>>(feat, K1, pS, K1, 1.0f / (N_OBJ - 1));
    depsum<<<1, 256>>>(dep);

    // U1 = (S/29) @ W2a  (split-K=16; reduce adds Sdep rank-1 + b1a)
    {
        int planeStride = 2 * TBM * DH1;
        gemm_tf32<<<dim3(DH1 / TBN, 2, 16), 256, GEMM_SMEM>>>(
            pS, K1, pW2ar, DH1, ppart, DH1, planeStride, BT, DH1, K1,
            nullptr, nullptr, nullptr, nullptr, 0);
        splitk_reduce<<<(BT * DH1 + 255) / 256, 256>>>(
            ppart, 16, planeStride, pU1, BT, DH1,
            pSdep, W2a + (size_t)K1 * DH1, nullptr, b1a, 0);
    }

    // H1 = relu(X @ Wc1 + depth*Wc1row4096 + U1[bt])  -- split-K=2 for occupancy
    {
        int mTiles = (MROWS + TBM - 1) / TBM;          // 47
        int planeStride = MROWS * DH1;                 // 3.07M floats/plane
        gemm_tf32<<<dim3(DH1 / TBN, mTiles, 2), 256, GEMM_SMEM>>>(
            feat, K1, pWc1, DH1, ppart, DH1, planeStride, MROWS, DH1, K1,
            nullptr, nullptr, nullptr, nullptr, 0);
        splitk_reduce<<<(MROWS * DH1 + 255) / 256, 256>>>(
            ppart, 2, planeStride, pH1, MROWS, DH1,
            dep, pWc1 + (size_t)K1 * DH1, pU1, nullptr, 1);
    }

    // layer b
    colsum30<<<dim3(cs_grid(DH1), BT), 128>>>(pH1, DH1, pS1, DH1, 1.0f / (N_OBJ - 1));
    {
        int planeStride = 2 * TBM * DH2;
        gemm_tf32<<<dim3(DH2 / TBN, 2, 8), 256, GEMM_SMEM>>>(
            pS1, DH1, pW2br, DH2, ppart, DH2, planeStride, BT, DH2, DH1,
            nullptr, nullptr, nullptr, nullptr, 0);
        splitk_reduce<<<(BT * DH2 + 255) / 256, 256>>>(
            ppart, 8, planeStride, pU2, BT, DH2, nullptr, nullptr, nullptr, b1b, 0);
    }
    // H2 = relu(H1 @ Wc2 + U2[bt])  -- split-K=2 for occupancy
    {
        int mTiles = (MROWS + TBM - 1) / TBM;
        int planeStride = MROWS * DH2;
        gemm_tf32<<<dim3(DH2 / TBN, mTiles, 2), 256, GEMM_SMEM>>>(
            pH1, DH1, pWc2, DH2, ppart, DH2, planeStride, MROWS, DH2, DH1,
            nullptr, nullptr, nullptr, nullptr, 0);
        splitk_reduce<<<(MROWS * DH2 + 255) / 256, 256>>>(
            ppart, 2, planeStride, pH2, MROWS, DH2,
            nullptr, nullptr, pU2, nullptr, 1);
    }

    // pool
    colsum30<<<dim3(cs_grid(DH2), BT), 128>>>(pH2, DH2, pg, DH2, 1.0f / N_OBJ);

    // transformer (fused)
    qkv_kernel<<<BT, 256>>>(pg, Wq, Wk, Wv, pq, pk, pv);
    attn_kernel<<<dim3(T_LEN, BSZ_B * NH), 128>>>(pq, pk, pv, patt);
    tail_kernel<<<BT, 256>>>(patt, pg, Wo, ln1g, ln1b, Wf1, bf1, Wf2, bf2,
                             ln2g, ln2b, Wc, bc, out);

    if (out_size > BT) {
        int rem = out_size - BT;
        zerofill<<<(rem + 255) / 256, 256>>>(out + BT, rem);
    }
}

// round 17
// speedup vs baseline: 1.1768x; 1.0033x over previous
#include <cuda_runtime.h>
#include <cuda_bf16.h>

// ---------------- problem constants ----------------
#define BSZ_B 2
#define T_LEN 100
#define N_OBJ 30
#define BT    (BSZ_B * T_LEN)      // 200
#define MROWS (BT * N_OBJ)         // 6000
#define K1    4096
#define DH1   512
#define DH2   256
#define DFF   512
#define NH    4
#define DHEAD 64

// ---------------- GEMM tiling ----------------
#define TBM 128
#define TBN 128
#define TBK 32
#define NS  3                       // pipeline stages
#define LDA_S 36                    // smem A row stride (floats)
#define BSZT 4096                   // packed B stage size (floats, 16KB)
#define ASZ  (TBM * LDA_S)          // 4608 floats / stage
#define GEMM_SMEM (NS * (ASZ + BSZT) * 4)   // 104448 bytes -> 2 CTAs/SM

// ---------------- scratch (device globals; no runtime alloc) ----------------
__device__ __align__(16) float g_Wc1[(K1 + 1) * DH1];   // tf32(W1a - W2a/29)
__device__ __align__(16) float g_W2ar[(K1 + 1) * DH1];  // tf32(W2a)
__device__ __align__(16) float g_Wc2[DH1 * DH2];        // tf32(W1b - W2b/29)
__device__ __align__(16) float g_W2br[DH1 * DH2];       // tf32(W2b)
__device__ __align__(16) float g_Wc1P[K1 * DH1];        // fragment-packed
__device__ __align__(16) float g_W2aP[K1 * DH1];
__device__ __align__(16) float g_Wc2P[DH1 * DH2];
__device__ __align__(16) float g_W2bP[DH1 * DH2];
__device__ __align__(16) float g_S[BT * K1];
__device__ __align__(16) float g_Sdep[BT];
__device__ __align__(16) float g_U1[BT * DH1];
__device__ __align__(16) float g_H1[MROWS * DH1];
__device__ __align__(16) float g_S1[BT * DH1];
__device__ __align__(16) float g_U2[BT * DH2];
__device__ __align__(16) float g_H2[MROWS * DH2];
__device__ __align__(16) float g_gp[BT * DH2];
__device__ __align__(16) float g_q[BT * DH2];
__device__ __align__(16) float g_k[BT * DH2];
__device__ __align__(16) float g_v[BT * DH2];
__device__ __align__(16) float g_att[BT * DH2];
__device__ __align__(16) float g_part[4 * MROWS * DH1]; // split-K partials (49MB)

// ---------------- helpers ----------------
__device__ __forceinline__ unsigned f2tf(float f) {
    unsigned u;
    asm("cvt.rna.tf32.f32 %0, %1;" : "=r"(u) : "f"(f));
    return u;
}

__device__ __forceinline__ void mma_tf32(float* d, const unsigned* a, const unsigned* b) {
    asm volatile(
        "mma.sync.aligned.m16n8k8.row.col.f32.tf32.tf32.f32 "
        "{%0,%1,%2,%3}, {%4,%5,%6,%7}, {%8,%9}, {%0,%1,%2,%3};"
        : "+f"(d[0]), "+f"(d[1]), "+f"(d[2]), "+f"(d[3])
        : "r"(a[0]), "r"(a[1]), "r"(a[2]), "r"(a[3]), "r"(b[0]), "r"(b[1]));
}

__device__ __forceinline__ float blocksum256(float v, float* buf) {
    int tid = threadIdx.x;
    buf[tid] = v;
    __syncthreads();
    for (int s = 128; s > 0; s >>= 1) {
        if (tid < s) buf[tid] += buf[tid + s];
        __syncthreads();
    }
    float r = buf[0];
    __syncthreads();
    return r;
}

// ---------------- prep: combined + tf32-prerounded weights ----------------
__global__ void prep_wc(const float* __restrict__ W1a, const float* __restrict__ W2a,
                        const float* __restrict__ W1b, const float* __restrict__ W2b) {
    const float inv = 1.0f / (N_OBJ - 1);
    int stride = gridDim.x * blockDim.x;
    int n1 = (K1 + 1) * DH1;
    for (int i = blockIdx.x * blockDim.x + threadIdx.x; i < n1; i += stride) {
        float w2 = W2a[i];
        g_Wc1[i]  = __uint_as_float(f2tf(W1a[i] - w2 * inv));
        g_W2ar[i] = __uint_as_float(f2tf(w2));
    }
    int n2 = DH1 * DH2;
    for (int i = blockIdx.x * blockDim.x + threadIdx.x; i < n2; i += stride) {
        float w2 = W2b[i];
        g_Wc2[i]  = __uint_as_float(f2tf(W1b[i] - w2 * inv));
        g_W2br[i] = __uint_as_float(f2tf(w2));
    }
}

// ---------------- fragment-pack B: W[K][N] -> tiles [N/128][K/32][4096] --------
// packed float offset within 4096-block:
//   2048*w + 1024*jhi + 256*qrh + 64*khi + 32*qrl + 4*((klo+4*qrl)&7) + jlo
// where n = bt*128 + w*64 + (jhi*4+jlo)*8 + (qrh*2+qrl), k = kt*32 + khi*8 + klo
__global__ void pack_b(const float* __restrict__ W, float* __restrict__ Wp,
                       int K, int N) {
    int stride = gridDim.x * blockDim.x;
    int total = K * N;
    for (int idx = blockIdx.x * blockDim.x + threadIdx.x; idx < total; idx += stride) {
        int k = idx / N, n = idx - k * N;
        int bt = n >> 7, nl = n & 127;
        int kt = k >> 5, kl = k & 31;
        int w = nl >> 6, rem = nl & 63;
        int j = rem >> 3, qr = rem & 7;
        int jlo = j & 3, jhi = j >> 2;
        int klo = kl & 7, khi = kl >> 3;
        int qrl = qr & 1, qrh = qr >> 1;
        int e = (klo + 4 * qrl) & 7;
        int off = 2048 * w + 1024 * jhi + 256 * qrh + 64 * khi + 32 * qrl + 4 * e + jlo;
        Wp[((size_t)(bt * (K >> 5) + kt) << 12) + off] = W[idx];
    }
}

// ---------------- column sum over 30 objects (float4 vectorized) ----------------
__global__ void colsum30(const float* __restrict__ src, int ld, float* __restrict__ out,
                         int cols, float scale) {
    int bt = blockIdx.y;
    int c4 = blockIdx.x * blockDim.x + threadIdx.x;
    if (c4 * 4 >= cols) return;
    const float4* p = (const float4*)(src + (size_t)bt * N_OBJ * ld) + c4;
    int ld4 = ld >> 2;
    float4 a = make_float4(0.f, 0.f, 0.f, 0.f);
#pragma unroll
    for (int n = 0; n < N_OBJ; n++) {
        float4 v = p[(size_t)n * ld4];
        a.x += v.x; a.y += v.y; a.z += v.z; a.w += v.w;
    }
    a.x *= scale; a.y *= scale; a.z *= scale; a.w *= scale;
    ((float4*)(out + (size_t)bt * cols))[c4] = a;
}

__global__ void depsum(const float* __restrict__ dep) {
    int bt = blockIdx.x * blockDim.x + threadIdx.x;
    if (bt < BT) {
        float s = 0.f;
#pragma unroll
        for (int n = 0; n < N_OBJ; n++) s += dep[bt * N_OBJ + n];
        g_Sdep[bt] = s * (1.0f / (N_OBJ - 1));
    }
}

// ---------------- tf32 tensor-core GEMM, packed-B, 3-stage, 2 CTAs/SM ----------
// Bp: fragment-packed tf32 weights. A cvt'd in-loop.
// direct (gridDim.z==1): C = A@B + rvec[m]*extw[n] + grp[m/30][n] + bias[n], relu opt.
// split-K (gridDim.z>1): raw partials to C + z*planeStride.
__global__ void __launch_bounds__(256, 2)
gemm_tf32(const float* __restrict__ A, int lda,
          const float* __restrict__ Bp,
          float* __restrict__ C, int ldc, int planeStride,
          int M, int N, int K,
          const float* __restrict__ rvec, const float* __restrict__ extw,
          const float* __restrict__ grp, const float* __restrict__ bias,
          int relu) {
    extern __shared__ float smem[];
    float* sA = smem;                 // [NS][TBM][LDA_S]
    float* sB = smem + NS * ASZ;      // [NS][4096] packed

    const int tid = threadIdx.x;
    const int bM = blockIdx.y * TBM;
    const int bN = blockIdx.x * TBN;
    const int warp = tid >> 5, lane = tid & 31;
    const int wm = (warp >> 1) * 32;    // 4 warps in M
    const int wn = (warp & 1) * 64;     // 2 warps in N
    const int qr = lane >> 2, qc = lane & 3;
    const int qrl = qr & 1, qrh = qr >> 1;
    const int bb = 512 * (warp & 1) + 64 * qrh + 8 * qrl;   // uint4 base
    const int e0 = (qc + 4 * qrl) & 7;
    const int e1 = e0 ^ 4;

    float acc[2][8][4];
#pragma unroll
    for (int i = 0; i < 2; i++)
#pragma unroll
        for (int j = 0; j < 8; j++)
#pragma unroll
            for (int e = 0; e < 4; e++) acc[i][j][e] = 0.f;

    const int KTglob = K / TBK;
    int KT = KTglob, kt0 = 0;
    if (gridDim.z > 1) { KT = KTglob / gridDim.z; kt0 = blockIdx.z * KT; }

    auto stage = [&](int buf, int kt) {
#pragma unroll
        for (int i = 0; i < 4; i++) {          // A: 1024 float4
            int id = tid + 256 * i;
            int r = id >> 3, c4 = id & 7;
            int gm = bM + r;
            int gmc = gm < M ? gm : (M - 1);
            const float* src = A + (size_t)gmc * lda + (size_t)kt * TBK + c4 * 4;
            unsigned dst = (unsigned)__cvta_generic_to_shared(sA + buf * ASZ + r * LDA_S + c4 * 4);
            int sz = (gm < M) ? 16 : 0;
            asm volatile("cp.async.cg.shared.global [%0], [%1], 16, %2;\n"
                         :: "r"(dst), "l"(src), "r"(sz));
        }
        const float* bsrc = Bp + (((size_t)(blockIdx.x * KTglob + kt)) << 12);
#pragma unroll
        for (int i = 0; i < 4; i++) {          // B: straight 16KB copy
            int id = tid + 256 * i;
            const float* src = bsrc + id * 4;
            unsigned dst = (unsigned)__cvta_generic_to_shared(sB + buf * BSZT + id * 4);
            asm volatile("cp.async.cg.shared.global [%0], [%1], 16, 16;\n"
                         :: "r"(dst), "l"(src));
        }
        asm volatile("cp.async.commit_group;\n" ::: "memory");
    };

#pragma unroll
    for (int s = 0; s < NS - 1; s++) {
        if (s < KT) stage(s, kt0 + s);
        else asm volatile("cp.async.commit_group;\n" ::: "memory");
    }

    for (int kt = 0; kt < KT; kt++) {
        asm volatile("cp.async.wait_group %0;\n" :: "n"(NS - 2) : "memory");
        __syncthreads();

        int nk = kt + NS - 1;
        if (nk < KT) stage(nk % NS, kt0 + nk);
        else asm volatile("cp.async.commit_group;\n" ::: "memory");

        const float* As = sA + (kt % NS) * ASZ;
        const uint4* Bs4 = (const uint4*)(sB + (kt % NS) * BSZT);

#pragma unroll
        for (int ks = 0; ks < 4; ks++) {
            const int k0 = ks * 8;
            unsigned af[2][4];
#pragma unroll
            for (int i = 0; i < 2; i++) {
                int r = wm + i * 16 + qr;
                af[i][0] = f2tf(As[r * LDA_S + k0 + qc]);
                af[i][1] = f2tf(As[(r + 8) * LDA_S + k0 + qc]);
                af[i][2] = f2tf(As[r * LDA_S + k0 + qc + 4]);
                af[i][3] = f2tf(As[(r + 8) * LDA_S + k0 + qc + 4]);
            }
            uint4 b00 = Bs4[bb + 16 * ks + e0];          // bf[0..3][0]
            uint4 b01 = Bs4[bb + 16 * ks + e1];          // bf[0..3][1]
            uint4 b10 = Bs4[bb + 256 + 16 * ks + e0];    // bf[4..7][0]
            uint4 b11 = Bs4[bb + 256 + 16 * ks + e1];    // bf[4..7][1]
            unsigned bf[8][2] = {
                {b00.x, b01.x}, {b00.y, b01.y}, {b00.z, b01.z}, {b00.w, b01.w},
                {b10.x, b11.x}, {b10.y, b11.y}, {b10.z, b11.z}, {b10.w, b11.w}};
#pragma unroll
            for (int i = 0; i < 2; i++)
#pragma unroll
                for (int j = 0; j < 8; j++) mma_tf32(acc[i][j], af[i], bf[j]);
        }
    }

    float* Cout = C + (gridDim.z > 1 ? (size_t)blockIdx.z * planeStride : 0);
    const int raw = (gridDim.z > 1);
#pragma unroll
    for (int i = 0; i < 2; i++) {
        int m0 = bM + wm + i * 16 + qr;
#pragma unroll
        for (int j = 0; j < 8; j++) {
            int n0 = bN + wn + j * 8 + qc * 2;
#pragma unroll
            for (int r2 = 0; r2 < 2; r2++) {
                int m = m0 + r2 * 8;
                if (m < M) {
#pragma unroll
                    for (int c2 = 0; c2 < 2; c2++) {
                        int n = n0 + c2;
                        float v = acc[i][j][r2 * 2 + c2];
                        if (!raw) {
                            if (rvec) v += rvec[m] * extw[n];
                            if (grp)  v += grp[(size_t)(m / N_OBJ) * ldc + n];
                            if (bias) v += bias[n];
                            if (relu) v = fmaxf(v, 0.f);
                        }
                        Cout[(size_t)m * ldc + n] = v;
                    }
                }
            }
        }
    }
}

// ---------------- split-K reduce with full epilogue ----------------
__global__ void splitk_reduce(const float* __restrict__ part, int planes, int planeStride,
                              float* __restrict__ C, int M, int N,
                              const float* __restrict__ rvec, const float* __restrict__ extw,
                              const float* __restrict__ grp, const float* __restrict__ bias,
                              int relu) {
    int idx = blockIdx.x * blockDim.x + threadIdx.x;
    if (idx >= M * N) return;
    int m = idx / N, n = idx - m * N;
    float s = 0.f;
    for (int z = 0; z < planes; z++) s += part[(size_t)z * planeStride + (size_t)m * N + n];
    if (rvec) s += rvec[m] * extw[n];
    if (grp)  s += grp[(size_t)(m / N_OBJ) * N + n];
    if (bias) s += bias[n];
    if (relu) s = fmaxf(s, 0.f);
    C[(size_t)m * N + n] = s;
}

// ---------------- fused q/k/v projection ----------------
__global__ void qkv_kernel(const float* __restrict__ g, const float* __restrict__ Wq,
                           const float* __restrict__ Wk, const float* __restrict__ Wv,
                           float* __restrict__ q, float* __restrict__ k,
                           float* __restrict__ v) {
    __shared__ float sg[DH2];
    int m = blockIdx.x, tid = threadIdx.x;
    sg[tid] = g[(size_t)m * DH2 + tid];
    __syncthreads();
    float aq = 0.f, ak = 0.f, av = 0.f;
#pragma unroll 4
    for (int kk = 0; kk < DH2; kk++) {
        float x = sg[kk];
        aq += x * Wq[(size_t)kk * DH2 + tid];
        ak += x * Wk[(size_t)kk * DH2 + tid];
        av += x * Wv[(size_t)kk * DH2 + tid];
    }
    q[(size_t)m * DH2 + tid] = aq;
    k[(size_t)m * DH2 + tid] = ak;
    v[(size_t)m * DH2 + tid] = av;
}

// ---------------- attention ----------------
__global__ void attn_kernel(const float* __restrict__ q, const float* __restrict__ k,
                            const float* __restrict__ v, float* __restrict__ o) {
    int t = blockIdx.x;
    int bh = blockIdx.y;
    int b = bh >> 2, h = bh & 3;
    __shared__ float sq[DHEAD];
    __shared__ float sp[128];
    __shared__ float buf[128];
    int tid = threadIdx.x;
    int rowbase = (b * T_LEN + t) * DH2 + h * DHEAD;
    if (tid < DHEAD) sq[tid] = q[rowbase + tid];
    __syncthreads();
    float sc = -1e30f;
    if (tid < T_LEN) {
        const float* kr = k + (b * T_LEN + tid) * DH2 + h * DHEAD;
        float d = 0.f;
#pragma unroll
        for (int j = 0; j < DHEAD; j++) d += sq[j] * kr[j];
        sc = d * 0.125f;
    }
    buf[tid] = sc;
    __syncthreads();
    for (int s = 64; s > 0; s >>= 1) {
        if (tid < s) buf[tid] = fmaxf(buf[tid], buf[tid + s]);
        __syncthreads();
    }
    float mx = buf[0];
    __syncthreads();
    float e = (tid < T_LEN) ? expf(sc - mx) : 0.f;
    buf[tid] = e;
    __syncthreads();
    for (int s = 64; s > 0; s >>= 1) {
        if (tid < s) buf[tid] += buf[tid + s];
        __syncthreads();
    }
    float inv = 1.f / buf[0];
    __syncthreads();
    sp[tid] = e * inv;
    __syncthreads();
    if (tid < DHEAD) {
        float a = 0.f;
        for (int s = 0; s < T_LEN; s++)
            a += sp[s] * v[(b * T_LEN + s) * DH2 + h * DHEAD + tid];
        o[rowbase + tid] = a;
    }
}

// ---------------- fused tail ----------------
__global__ void tail_kernel(const float* __restrict__ att, const float* __restrict__ g,
                            const float* __restrict__ Wo,
                            const float* __restrict__ ln1g, const float* __restrict__ ln1b,
                            const float* __restrict__ Wf1, const float* __restrict__ bf1,
                            const float* __restrict__ Wf2, const float* __restrict__ bf2,
                            const float* __restrict__ ln2g, const float* __restrict__ ln2b,
                            const float* __restrict__ Wc, const float* __restrict__ bc,
                            float* __restrict__ out) {
    __shared__ float sctx[DH2];
    __shared__ float sy[DH2];
    __shared__ float sff[DFF];
    __shared__ float buf[256];
    int m = blockIdx.x, tid = threadIdx.x;

    sctx[tid] = att[(size_t)m * DH2 + tid];
    __syncthreads();
    float p = 0.f;
#pragma unroll 4
    for (int kk = 0; kk < DH2; kk++) p += sctx[kk] * Wo[(size_t)kk * DH2 + tid];
    float v = g[(size_t)m * DH2 + tid] + p;
    float mu = blocksum256(v, buf) * (1.f / DH2);
    float d = v - mu;
    float var = blocksum256(d * d, buf) * (1.f / DH2);
    float y = d * rsqrtf(var + 1e-5f) * ln1g[tid] + ln1b[tid];
    sy[tid] = y;
    __syncthreads();
#pragma unroll
    for (int jj = 0; jj < 2; jj++) {
        int j = tid + jj * 256;
        float a = 0.f;
#pragma unroll 4
        for (int kk = 0; kk < DH2; kk++) a += sy[kk] * Wf1[(size_t)kk * DFF + j];
        sff[j] = fmaxf(a + bf1[j], 0.f);
    }
    __syncthreads();
    float a2 = 0.f;
#pragma unroll 4
    for (int kk = 0; kk < DFF; kk++) a2 += sff[kk] * Wf2[(size_t)kk * DH2 + tid];
    a2 += bf2[tid];
    float v2 = y + a2;
    float mu2 = blocksum256(v2, buf) * (1.f / DH2);
    float d2 = v2 - mu2;
    float var2 = blocksum256(d2 * d2, buf) * (1.f / DH2);
    float z = d2 * rsqrtf(var2 + 1e-5f) * ln2g[tid] + ln2b[tid];
    float s = blocksum256(z * Wc[tid], buf);
    if (tid == 0) out[m] = 1.f / (1.f + expf(-(s + bc[0])));
}

__global__ void zerofill(float* __restrict__ p, int n) {
    int i = blockIdx.x * blockDim.x + threadIdx.x;
    if (i < n) p[i] = 0.f;
}

static inline int cs_grid(int cols) {
    int v = (cols / 4 + 127) / 128;
    return v < 1 ? 1 : v;
}

// ---------------- launch ----------------
extern "C" void kernel_launch(void* const* d_in, const int* in_sizes, int n_in,
                              void* d_out, int out_size) {
    const float* feat = (const float*)d_in[0];
    const float* dep  = (const float*)d_in[1];
    const float* W1a = (const float*)d_in[2];
    const float* W2a = (const float*)d_in[3];
    const float* b1a = (const float*)d_in[4];
    const float* W1b = (const float*)d_in[5];
    const float* W2b = (const float*)d_in[6];
    const float* b1b = (const float*)d_in[7];
    const float* Wq = (const float*)d_in[8];
    const float* Wk = (const float*)d_in[9];
    const float* Wv = (const float*)d_in[10];
    const float* Wo = (const float*)d_in[11];
    const float* ln1g = (const float*)d_in[12];
    const float* ln1b = (const float*)d_in[13];
    const float* Wf1 = (const float*)d_in[14];
    const float* bf1 = (const float*)d_in[15];
    const float* Wf2 = (const float*)d_in[16];
    const float* bf2 = (const float*)d_in[17];
    const float* ln2g = (const float*)d_in[18];
    const float* ln2b = (const float*)d_in[19];
    const float* Wc = (const float*)d_in[20];
    const float* bc = (const float*)d_in[21];
    float* out = (float*)d_out;

    float *pWc1, *pW2ar, *pWc2, *pW2br, *pWc1P, *pW2aP, *pWc2P, *pW2bP;
    float *pS, *pSdep, *pU1, *pH1, *pS1, *pU2, *pH2, *pg;
    float *pq, *pk, *pv, *patt, *ppart;
    cudaGetSymbolAddress((void**)&pWc1, g_Wc1);
    cudaGetSymbolAddress((void**)&pW2ar, g_W2ar);
    cudaGetSymbolAddress((void**)&pWc2, g_Wc2);
    cudaGetSymbolAddress((void**)&pW2br, g_W2br);
    cudaGetSymbolAddress((void**)&pWc1P, g_Wc1P);
    cudaGetSymbolAddress((void**)&pW2aP, g_W2aP);
    cudaGetSymbolAddress((void**)&pWc2P, g_Wc2P);
    cudaGetSymbolAddress((void**)&pW2bP, g_W2bP);
    cudaGetSymbolAddress((void**)&pS, g_S);
    cudaGetSymbolAddress((void**)&pSdep, g_Sdep);
    cudaGetSymbolAddress((void**)&pU1, g_U1);
    cudaGetSymbolAddress((void**)&pH1, g_H1);
    cudaGetSymbolAddress((void**)&pS1, g_S1);
    cudaGetSymbolAddress((void**)&pU2, g_U2);
    cudaGetSymbolAddress((void**)&pH2, g_H2);
    cudaGetSymbolAddress((void**)&pg, g_gp);
    cudaGetSymbolAddress((void**)&pq, g_q);
    cudaGetSymbolAddress((void**)&pk, g_k);
    cudaGetSymbolAddress((void**)&pv, g_v);
    cudaGetSymbolAddress((void**)&patt, g_att);
    cudaGetSymbolAddress((void**)&ppart, g_part);

    cudaFuncSetAttribute((const void*)gemm_tf32,
                         cudaFuncAttributeMaxDynamicSharedMemorySize, GEMM_SMEM);

    // combined + pre-rounded weights, fragment packing, neighbor sums
    prep_wc<<<1024, 256>>>(W1a, W2a, W1b, W2b);
    pack_b<<<1024, 256>>>(pWc1, pWc1P, K1, DH1);
    pack_b<<<1024, 256>>>(pW2ar, pW2aP, K1, DH1);
    pack_b<<<256, 256>>>(pWc2, pWc2P, DH1, DH2);
    pack_b<<<256, 256>>>(pW2br, pW2bP, DH1, DH2);
    colsum30<<<dim3(cs_grid(K1), BT), 128>>>(feat, K1, pS, K1, 1.0f / (N_OBJ - 1));
    depsum<<<1, 256>>>(dep);

    // U1 = (S/29) @ W2a  (split-K=16; reduce adds Sdep rank-1 + b1a)
    {
        int planeStride = 2 * TBM * DH1;
        gemm_tf32<<<dim3(DH1 / TBN, 2, 16), 256, GEMM_SMEM>>>(
            pS, K1, pW2aP, ppart, DH1, planeStride, BT, DH1, K1,
            nullptr, nullptr, nullptr, nullptr, 0);
        splitk_reduce<<<(BT * DH1 + 255) / 256, 256>>>(
            ppart, 16, planeStride, pU1, BT, DH1,
            pSdep, W2a + (size_t)K1 * DH1, nullptr, b1a, 0);
    }

    // H1 = relu(X @ Wc1 + depth*Wc1row4096 + U1[bt])  -- split-K=4
    {
        int mTiles = (MROWS + TBM - 1) / TBM;          // 47
        int planeStride = MROWS * DH1;
        gemm_tf32<<<dim3(DH1 / TBN, mTiles, 4), 256, GEMM_SMEM>>>(
            feat, K1, pWc1P, ppart, DH1, planeStride, MROWS, DH1, K1,
            nullptr, nullptr, nullptr, nullptr, 0);
        splitk_reduce<<<(MROWS * DH1 + 255) / 256, 256>>>(
            ppart, 4, planeStride, pH1, MROWS, DH1,
            dep, pWc1 + (size_t)K1 * DH1, pU1, nullptr, 1);
    }

    // layer b
    colsum30<<<dim3(cs_grid(DH1), BT), 128>>>(pH1, DH1, pS1, DH1, 1.0f / (N_OBJ - 1));
    {
        int planeStride = 2 * TBM * DH2;
        gemm_tf32<<<dim3(DH2 / TBN, 2, 8), 256, GEMM_SMEM>>>(
            pS1, DH1, pW2bP, ppart, DH2, planeStride, BT, DH2, DH1,
            nullptr, nullptr, nullptr, nullptr, 0);
        splitk_reduce<<<(BT * DH2 + 255) / 256, 256>>>(
            ppart, 8, planeStride, pU2, BT, DH2, nullptr, nullptr, nullptr, b1b, 0);
    }
    // H2 = relu(H1 @ Wc2 + U2[bt])  -- split-K=2
    {
        int mTiles = (MROWS + TBM - 1) / TBM;
        int planeStride = MROWS * DH2;
        gemm_tf32<<<dim3(DH2 / TBN, mTiles, 2), 256, GEMM_SMEM>>>(
            pH1, DH1, pWc2P, ppart, DH2, planeStride, MROWS, DH2, DH1,
            nullptr, nullptr, nullptr, nullptr, 0);
        splitk_reduce<<<(MROWS * DH2 + 255) / 256, 256>>>(
            ppart, 2, planeStride, pH2, MROWS, DH2,
            nullptr, nullptr, pU2, nullptr, 1);
    }

    // pool
    colsum30<<<dim3(cs_grid(DH2), BT), 128>>>(pH2, DH2, pg, DH2, 1.0f / N_OBJ);

    // transformer (fused)
    qkv_kernel<<<BT, 256>>>(pg, Wq, Wk, Wv, pq, pk, pv);
    attn_kernel<<<dim3(T_LEN, BSZ_B * NH), 128>>>(pq, pk, pv, patt);
    tail_kernel<<<BT, 256>>>(patt, pg, Wo, ln1g, ln1b, Wf1, bf1, Wf2, bf2,
                             ln2g, ln2b, Wc, bc, out);

    if (out_size > BT) {
        int rem = out_size - BT;
        zerofill<<<(rem + 255) / 256, 256>>>(out + BT, rem);
    }
}